// round 14
// baseline (speedup 1.0000x reference)
#include <cuda_runtime.h>
#include <cstdint>
#include <cstddef>

#define T_STEPS 2048
#define HID     128
#define BATCH   256

typedef unsigned long long ull;

// folded FC, transposed planes: M0[128], M1[128], M2[128], c[3]
__device__ __align__(16) float g_fold[3 * 128 + 4];

// ---- packed f32x2 helpers ----
__device__ __forceinline__ ull fma2(ull a, ull b, ull c) {
    ull d;
    asm("fma.rn.f32x2 %0, %1, %2, %3;" : "=l"(d) : "l"(a), "l"(b), "l"(c));
    return d;
}
__device__ __forceinline__ ull add2(ull a, ull b) {
    ull d;
    asm("add.rn.f32x2 %0, %1, %2;" : "=l"(d) : "l"(a), "l"(b));
    return d;
}
__device__ __forceinline__ void unpack2(ull u, float& x, float& y) {
    asm("mov.b64 {%0, %1}, %2;" : "=f"(x), "=f"(y) : "l"(u));
}

// tanh via MUFU: tanh(|x|) = (1-e)/(1+e), e = exp(-2|x|)
__device__ __forceinline__ float fast_tanh(float x) {
    float ax = fabsf(x);
    float e  = __expf(-2.0f * ax);
    float r  = __fdividef(1.0f - e, 1.0f + e);
    return copysignf(r, x);
}

__global__ void fold_kernel(const float* __restrict__ W_fc1,
                            const float* __restrict__ b_fc1,
                            const float* __restrict__ W_fc2,
                            const float* __restrict__ b_fc2) {
    int h = threadIdx.x;  // 0..127
    float m0 = 0.f, m1 = 0.f, m2 = 0.f;
    #pragma unroll 8
    for (int f = 0; f < 64; f++) {
        float w = W_fc1[f * 128 + h];
        m0 = fmaf(w, W_fc2[0 * 64 + f], m0);
        m1 = fmaf(w, W_fc2[1 * 64 + f], m1);
        m2 = fmaf(w, W_fc2[2 * 64 + f], m2);
    }
    g_fold[0 * 128 + h] = m0;
    g_fold[1 * 128 + h] = m1;
    g_fold[2 * 128 + h] = m2;
    if (h < 3) {
        float c = b_fc2[h];
        for (int f = 0; f < 64; f++) c = fmaf(b_fc1[f], W_fc2[h * 64 + f], c);
        g_fold[384 + h] = c;
    }
}

// shared layout (floats):
//   x4   : 2*2048*4          = 16384 @ 0      (x padded to float4)
//   h    : 2(grp)*2(par)*128 = 512   @ 16384  (per-group ping-pong)
//   ring : 2(grp)*2(half)*64*130 = 33280 @ 16896
//   M    : 384 @ 50176 ; c : 4 @ 50560
#define OFF_H     16384
#define OFF_RING  16896
#define RING_ROW  (64 * 130)      // 8320
#define RING_G    (2 * RING_ROW)  // 16640 per group (2 halves)
#define OFF_M     50176
#define OFF_C     50560
#define SMEM_FLOATS 50564
#define SMEM_BYTES  (SMEM_FLOATS * 4)

__device__ __forceinline__ void group_bar(int g) {
    asm volatile("bar.sync %0, %1;" :: "r"(g + 1), "r"(128) : "memory");
}

__global__ __launch_bounds__(256, 1)
void rnn_kernel(const float* __restrict__ x,
                const float* __restrict__ hidden,
                const float* __restrict__ W_ih,
                const float* __restrict__ W_hh,
                const float* __restrict__ b_ih,
                const float* __restrict__ b_hh,
                float* __restrict__ out) {
    extern __shared__ float sm[];
    float4* x4v  = (float4*)sm;          // [2][2048]
    float*  h_sh = sm + OFF_H;           // [grp][parity][128]
    float*  ring = sm + OFF_RING;        // [grp][half][64][130]
    float*  Msh  = sm + OFF_M;           // [3][128]
    float*  csh  = sm + OFF_C;           // [3]

    const int tid = threadIdx.x;
    const int g   = tid >> 7;            // row-group (0/1) == local row
    const int j   = tid & 127;           // hidden index this thread owns
    const int r0  = blockIdx.x * 2;
    const int r   = r0 + g;              // my batch row

    // stage x for both rows, padded to float4
    for (int base = tid; base < 2 * T_STEPS; base += 256) {
        int row = base >> 11, t = base & 2047;
        const float* p = x + ((size_t)(r0 + row) * T_STEPS + t) * 3;
        x4v[row * T_STEPS + t] = make_float4(p[0], p[1], p[2], 0.f);
    }
    for (int idx = tid; idx < 384; idx += 256) Msh[idx] = g_fold[idx];
    if (tid < 3) csh[tid] = g_fold[384 + tid];

    // initial hidden -> my group's parity-0 buffer
    h_sh[g * 256 + j] = hidden[(size_t)r * HID + j];

    // W_hh row j in registers (64 packed f32x2) -- same for both groups
    ull w[64];
    const ull* wrow = (const ull*)(W_hh + j * HID);
    #pragma unroll
    for (int i = 0; i < 64; i++) w[i] = wrow[i];

    const float wi0 = W_ih[j * 3 + 0];
    const float wi1 = W_ih[j * 3 + 1];
    const float wi2 = W_ih[j * 3 + 2];
    const float bc  = b_ih[j] + b_hh[j];

    float*       hg    = h_sh + g * 256;       // [parity][128]
    float*       ringg = ring + g * RING_G;    // [half][64][130]
    const float4* xg   = x4v + g * T_STEPS;
    const float* fcb   = ringg + j * 130;      // FC base (valid for j<64)

    ull oa0 = 0, oa1 = 0, oa2 = 0;             // smeared-FC accumulators

    __syncthreads();   // staging visible to all (only full-block barrier)

    // skew group 1 by ~256 cyc so the groups' stall windows anti-phase.
    // dependent FMA chain; fold result into hg so the first h-load waits on it.
    if (g) {
        float z = (float)j;
        #pragma unroll
        for (int i = 0; i < 64; i++) z = fmaf(z, 0.9999f, 1.0f);
        hg += (z > 1e30f) ? 1 : 0;   // always +0, but unprovable at compile time
    }

    // one RNN step for my row; doFC consumes 2 ring entries of the opposite half
    auto step = [&](int t, int tl, int p, int wh, bool doFC) {
        float4 xa = xg[t];
        float s = fmaf(wi2, xa.z, fmaf(wi1, xa.y, fmaf(wi0, xa.x, bc)));

        if (doFC && j < 64) {  // independent of h -> fills stall shadows
            int k2 = tl * 2;
            ull rp = *(const ull*)(fcb + (wh ^ 1) * RING_ROW * 0 + (wh ^ 1) * RING_ROW + k2 - (wh ^ 1) * RING_ROW + (wh ^ 1) * RING_ROW);
            // (simplified below; kept single expression for the optimizer)
            rp = *(const ull*)(fcb + (wh ^ 1) * RING_ROW + k2);
            oa0 = fma2(rp, *(const ull*)(Msh + k2),       oa0);
            oa1 = fma2(rp, *(const ull*)(Msh + 128 + k2), oa1);
            oa2 = fma2(rp, *(const ull*)(Msh + 256 + k2), oa2);
        }

        // h . W_hh[j]: 64 packed f32x2 FMAs, 4 independent chains
        ull a0 = 0, a1 = 0, a2 = 0, a3 = 0;
        const ulonglong2* hv = (const ulonglong2*)(hg + p * 128);
        #pragma unroll
        for (int i = 0; i < 32; i++) {
            ulonglong2 v = hv[i];
            if (i & 1) {
                a2 = fma2(v.x, w[2 * i], a2);
                a3 = fma2(v.y, w[2 * i + 1], a3);
            } else {
                a0 = fma2(v.x, w[2 * i], a0);
                a1 = fma2(v.y, w[2 * i + 1], a1);
            }
        }
        ull ra = add2(add2(a0, a2), add2(a1, a3));
        float f0, f1;
        unpack2(ra, f0, f1);
        float hn = fast_tanh(s + (f0 + f1));

        hg[(p ^ 1) * 128 + j] = hn;
        ringg[wh * RING_ROW + tl * 130 + j] = hn;
        group_bar(g);   // ONLY my group's 4 warps synchronize
    };

    // window 0: no FC consumption yet (ring half 0 being filled)
    #pragma unroll 2
    for (int tl = 0; tl < 64; tl++) step(tl, tl, tl & 1, 0, false);

    // windows 1..31: smear FC of previous window, finalize at window end
    for (int wdw = 1; wdw < 32; wdw++) {
        const int wh = wdw & 1;
        #pragma unroll 2
        for (int tl = 0; tl < 64; tl++) step(wdw * 64 + tl, tl, tl & 1, wh, true);

        if (j < 64) {
            float f0a, f0b, f1a, f1b, f2a, f2b;
            unpack2(oa0, f0a, f0b);
            unpack2(oa1, f1a, f1b);
            unpack2(oa2, f2a, f2b);
            int tg = (wdw - 1) * 64 + j;
            float* op = out + ((size_t)r * T_STEPS + tg) * 3;
            op[0] = f0a + f0b + csh[0];
            op[1] = f1a + f1b + csh[1];
            op[2] = f2a + f2b + csh[2];
            oa0 = oa1 = oa2 = 0;
        }
    }

    // flush FC for the last window (stored in half 1)
    if (j < 64) {
        const float* rp0 = fcb + RING_ROW;
        #pragma unroll 8
        for (int k2 = 0; k2 < 128; k2 += 2) {
            ull rp = *(const ull*)(rp0 + k2);
            oa0 = fma2(rp, *(const ull*)(Msh + k2),       oa0);
            oa1 = fma2(rp, *(const ull*)(Msh + 128 + k2), oa1);
            oa2 = fma2(rp, *(const ull*)(Msh + 256 + k2), oa2);
        }
        float f0a, f0b, f1a, f1b, f2a, f2b;
        unpack2(oa0, f0a, f0b);
        unpack2(oa1, f1a, f1b);
        unpack2(oa2, f2a, f2b);
        int tg = 31 * 64 + j;
        float* op = out + ((size_t)r * T_STEPS + tg) * 3;
        op[0] = f0a + f0b + csh[0];
        op[1] = f1a + f1b + csh[1];
        op[2] = f2a + f2b + csh[2];
    }

    // final hidden state (even #steps -> parity-0 buffer)
    float* hT = out + (size_t)BATCH * T_STEPS * 3;
    hT[(size_t)r * HID + j] = hg[j];
}

extern "C" void kernel_launch(void* const* d_in, const int* in_sizes, int n_in,
                              void* d_out, int out_size) {
    const float* x      = (const float*)d_in[0];
    const float* hidden = (const float*)d_in[1];
    const float* W_ih   = (const float*)d_in[2];
    const float* W_hh   = (const float*)d_in[3];
    const float* b_ih   = (const float*)d_in[4];
    const float* b_hh   = (const float*)d_in[5];
    const float* W_fc1  = (const float*)d_in[6];
    const float* b_fc1  = (const float*)d_in[7];
    const float* W_fc2  = (const float*)d_in[8];
    const float* b_fc2  = (const float*)d_in[9];
    float* out = (float*)d_out;

    cudaFuncSetAttribute(rnn_kernel, cudaFuncAttributeMaxDynamicSharedMemorySize, SMEM_BYTES);

    fold_kernel<<<1, 128>>>(W_fc1, b_fc1, W_fc2, b_fc2);
    rnn_kernel<<<BATCH / 2, 256, SMEM_BYTES>>>(x, hidden, W_ih, W_hh, b_ih, b_hh, out);
}